// round 8
// baseline (speedup 1.0000x reference)
#include <cuda_runtime.h>
#include <cuda_bf16.h>
#include <cstdint>

// Problem constants
#define BB   2
#define TT   260
#define HH   4
#define DD   1024
#define VV   32000
#define DFF  2048
#define MM   512

// ---------------------------------------------------------------------------
// Persistent scratch (__device__ globals; no allocations allowed)
// ---------------------------------------------------------------------------
#define OFF_PROJ 0
#define OFF_SAWV 8388608
#define OFF_SAWO 12582912
#define OFF_CAWV 16777216
#define OFF_CAWO 20971520
#define OFF_FF1  25165824
#define OFF_FF2  33554432
#define OFF_UNE  41943040
#define W_TOTAL  74711040

__device__ __nv_bfloat16 g_whi[W_TOTAL];
__device__ __nv_bfloat16 g_wlo[W_TOTAL];

__device__ float g_x  [MM * DD];
__device__ float g_t2 [MM * DD];
__device__ __nv_bfloat16 g_xc_hi[MM * 2 * DD], g_xc_lo[MM * 2 * DD];
__device__ __nv_bfloat16 g_x_hi [HH][MM * DD], g_x_lo [HH][MM * DD]; // per-head
__device__ __nv_bfloat16 g_t1_hi[MM * DFF],    g_t1_lo[MM * DFF];

// ---------------------------------------------------------------------------
// helpers
// ---------------------------------------------------------------------------
__device__ __forceinline__ float block_sum(float v) {
    __shared__ float sh[32];
    const int lane = threadIdx.x & 31;
    const int wid  = threadIdx.x >> 5;
    #pragma unroll
    for (int o = 16; o; o >>= 1) v += __shfl_xor_sync(0xffffffffu, v, o);
    if (lane == 0) sh[wid] = v;
    __syncthreads();
    if (wid == 0) {
        v = (lane < 8) ? sh[lane] : 0.0f;
        #pragma unroll
        for (int o = 4; o; o >>= 1) v += __shfl_xor_sync(0xffffffffu, v, o);
        if (lane == 0) sh[0] = v;
    }
    __syncthreads();
    v = sh[0];
    __syncthreads();
    return v;
}

__device__ __forceinline__ uint32_t s2u(const void* p) {
    uint32_t a;
    asm("{ .reg .u64 t; cvta.to.shared.u64 t, %1; cvt.u32.u64 %0, t; }" : "=r"(a) : "l"(p));
    return a;
}
__device__ __forceinline__ void ldsm4(uint32_t* r, uint32_t addr) {
    asm volatile("ldmatrix.sync.aligned.m8n8.x4.shared.b16 {%0,%1,%2,%3}, [%4];"
                 : "=r"(r[0]), "=r"(r[1]), "=r"(r[2]), "=r"(r[3]) : "r"(addr));
}
__device__ __forceinline__ void mma_bf16(float* c, const uint32_t* a, const uint32_t* b) {
    asm volatile(
        "mma.sync.aligned.m16n8k16.row.col.f32.bf16.bf16.f32 "
        "{%0,%1,%2,%3}, {%4,%5,%6,%7}, {%8,%9}, {%0,%1,%2,%3};"
        : "+f"(c[0]), "+f"(c[1]), "+f"(c[2]), "+f"(c[3])
        : "r"(a[0]), "r"(a[1]), "r"(a[2]), "r"(a[3]), "r"(b[0]), "r"(b[1]));
}
__device__ __forceinline__ void split_bf(float f, __nv_bfloat16& h, __nv_bfloat16& l) {
    h = __float2bfloat16_rn(f);
    l = __float2bfloat16_rn(f - __bfloat162float(h));
}

// ---------------------------------------------------------------------------
// weight conversion: fp32 -> bf16 hi/lo
// ---------------------------------------------------------------------------
__global__ void conv_w(const float* __restrict__ src,
                       __nv_bfloat16* __restrict__ hi,
                       __nv_bfloat16* __restrict__ lo, int n4) {
    int i = blockIdx.x * blockDim.x + threadIdx.x;
    const int stride = gridDim.x * blockDim.x;
    for (; i < n4; i += stride) {
        float4 v = ((const float4*)src)[i];
        float f[4] = { v.x, v.y, v.z, v.w };
        uint32_t hp[2], lp[2];
        #pragma unroll
        for (int q = 0; q < 2; q++) {
            __nv_bfloat16 h0, l0, h1, l1;
            split_bf(f[2*q],   h0, l0);
            split_bf(f[2*q+1], h1, l1);
            hp[q] = (uint32_t)__bfloat16_as_ushort(h0) | ((uint32_t)__bfloat16_as_ushort(h1) << 16);
            lp[q] = (uint32_t)__bfloat16_as_ushort(l0) | ((uint32_t)__bfloat16_as_ushort(l1) << 16);
        }
        ((uint2*)hi)[i] = make_uint2(hp[0], hp[1]);
        ((uint2*)lo)[i] = make_uint2(lp[0], lp[1]);
    }
}

__global__ void init_h_kernel(const float* __restrict__ hidden, float* __restrict__ hbuf) {
    const int m = blockIdx.x;
    const int b = m >> 8, j = m & 255;
    const float* src = hidden + ((size_t)b * TT + j) * DD;
    float* dst = hbuf + (size_t)m * DD;
    #pragma unroll
    for (int i = 0; i < 4; i++) dst[threadIdx.x + i * 256] = src[threadIdx.x + i * 256];
}

__global__ void prep_kernel(const int* __restrict__ tok,
                            const float* __restrict__ emb,
                            const float* __restrict__ hprev,
                            const float* __restrict__ rms_w,
                            __nv_bfloat16* __restrict__ xch,
                            __nv_bfloat16* __restrict__ xcl, int h) {
    const int m = blockIdx.x;
    const int half = blockIdx.y;
    const int tid = threadIdx.x;
    const int b = m >> 8, j = m & 255;
    const float* src;
    if (half == 0) {
        const int t = tok[b * TT + 1 + h + j];
        src = emb + (size_t)t * DD;
    } else {
        src = hprev + (size_t)m * DD;
    }
    float v[4];
    float ss = 0.0f;
    #pragma unroll
    for (int i = 0; i < 4; i++) { v[i] = src[tid + i * 256]; ss += v[i] * v[i]; }
    ss = block_sum(ss);
    const float s = rsqrtf(ss * (1.0f / DD) + 1e-6f);
    const size_t base = (size_t)m * (2 * DD) + half * DD;
    #pragma unroll
    for (int i = 0; i < 4; i++) {
        const int d = tid + i * 256;
        const float f = v[i] * s * rms_w[d];
        __nv_bfloat16 hh, ll;
        split_bf(f, hh, ll);
        xch[base + d] = hh;
        xcl[base + d] = ll;
    }
}

__global__ void resid_ln_kernel(float* __restrict__ x, const float* __restrict__ u,
                                const float* __restrict__ w, const float* __restrict__ bb,
                                __nv_bfloat16* __restrict__ oh, __nv_bfloat16* __restrict__ ol) {
    const int m = blockIdx.x;
    const int tid = threadIdx.x;
    float* xr = x + (size_t)m * DD;
    const float* ur = u + (size_t)m * DD;
    float v[4];
    float s = 0.0f;
    #pragma unroll
    for (int i = 0; i < 4; i++) {
        v[i] = xr[tid + i * 256] + ur[tid + i * 256];
        s += v[i];
    }
    s = block_sum(s);
    const float mu = s * (1.0f / DD);
    float s2 = 0.0f;
    #pragma unroll
    for (int i = 0; i < 4; i++) { const float d = v[i] - mu; s2 += d * d; }
    s2 = block_sum(s2);
    const float rs = rsqrtf(s2 * (1.0f / DD) + 1e-5f);
    #pragma unroll
    for (int i = 0; i < 4; i++) {
        const int d = tid + i * 256;
        const float f = (v[i] - mu) * rs * w[d] + bb[d];
        xr[d] = f;
        __nv_bfloat16 hh, ll;
        split_bf(f, hh, ll);
        oh[(size_t)m * DD + d] = hh;
        ol[(size_t)m * DD + d] = ll;
    }
}

// ---------------------------------------------------------------------------
// bf16 split-precision GEMM (3-product emulation), cp.async S-stage pipeline.
// ---------------------------------------------------------------------------
template<int BM, int BN, int WGM, int WGN, int NTH, int S>
__global__ void __launch_bounds__(NTH) gemm_bf(
    const __nv_bfloat16* __restrict__ Ahi, const __nv_bfloat16* __restrict__ Alo,
    const __nv_bfloat16* __restrict__ Bhi, const __nv_bfloat16* __restrict__ Blo,
    const float* __restrict__ bias,
    float* __restrict__ C, long long ldc,
    __nv_bfloat16* __restrict__ Ohi, __nv_bfloat16* __restrict__ Olo, int ldo,
    int K, int relu)
{
    constexpr int WM  = BM / WGM;
    constexpr int WN  = BN / WGN;
    constexpr int MI  = WM / 16;
    constexpr int NI  = WN / 8;
    constexpr int LS  = 40;
    constexpr int AT  = BM * LS * 2;
    constexpr int BT  = BN * LS * 2;
    constexpr int STAGE = 2 * AT + 2 * BT;

    extern __shared__ char smem[];
    const uint32_t sb = s2u(smem);

    const int tid  = threadIdx.x;
    const int wid  = tid >> 5;
    const int lane = tid & 31;
    const int wm   = wid / WGN;
    const int wn   = wid % WGN;
    const int m0   = blockIdx.x * BM;
    const int n0   = blockIdx.y * BN;
    const int nCh  = K >> 5;

    float acc[MI][NI][4];
    #pragma unroll
    for (int i = 0; i < MI; i++)
        #pragma unroll
        for (int j = 0; j < NI; j++)
            #pragma unroll
            for (int q = 0; q < 4; q++) acc[i][j][q] = 0.0f;

    auto issue = [&](int c) {
        if (c < nCh) {
            const int k0 = c << 5;
            const uint32_t st = sb + (uint32_t)(c % S) * STAGE;
            #pragma unroll
            for (int q = tid; q < BM * 4; q += NTH) {
                const int row = q >> 2, col = (q & 3) << 3;
                const size_t off = (size_t)(m0 + row) * K + k0 + col;
                const uint32_t d = st + (uint32_t)(row * LS + col) * 2u;
                asm volatile("cp.async.cg.shared.global [%0], [%1], 16;" :: "r"(d), "l"(Ahi + off));
                asm volatile("cp.async.cg.shared.global [%0], [%1], 16;" :: "r"(d + AT), "l"(Alo + off));
            }
            #pragma unroll
            for (int q = tid; q < BN * 4; q += NTH) {
                const int row = q >> 2, col = (q & 3) << 3;
                const size_t off = (size_t)(n0 + row) * K + k0 + col;
                const uint32_t d = st + 2 * AT + (uint32_t)(row * LS + col) * 2u;
                asm volatile("cp.async.cg.shared.global [%0], [%1], 16;" :: "r"(d), "l"(Bhi + off));
                asm volatile("cp.async.cg.shared.global [%0], [%1], 16;" :: "r"(d + BT), "l"(Blo + off));
            }
        }
        asm volatile("cp.async.commit_group;" ::: "memory");
    };

    #pragma unroll
    for (int p = 0; p < S - 1; p++) issue(p);

    for (int c = 0; c < nCh; c++) {
        asm volatile("cp.async.wait_group %0;" :: "n"(S - 2) : "memory");
        __syncthreads();
        issue(c + S - 1);

        const uint32_t st  = sb + (uint32_t)(c % S) * STAGE;
        const uint32_t sAh = st;
        const uint32_t sBh = st + 2 * AT;
        #pragma unroll
        for (int ks = 0; ks < 2; ks++) {
            uint32_t ah[MI][4], al[MI][4];
            #pragma unroll
            for (int mi = 0; mi < MI; mi++) {
                const int row = wm * WM + mi * 16 + (lane & 15);
                const int col = ks * 16 + (lane >> 4) * 8;
                const uint32_t ad = sAh + (uint32_t)(row * LS + col) * 2u;
                ldsm4(ah[mi], ad);
                ldsm4(al[mi], ad + AT);
            }
            uint32_t bh[NI][2], bl[NI][2];
            #pragma unroll
            for (int ni = 0; ni < NI; ni += 2) {
                const int g = lane >> 3;
                const int row = wn * WN + ni * 8 + ((g >> 1) << 3) + (lane & 7);
                const int col = ks * 16 + ((g & 1) << 3);
                const uint32_t bd = sBh + (uint32_t)(row * LS + col) * 2u;
                ldsm4(&bh[ni][0], bd);
                ldsm4(&bl[ni][0], bd + BT);
            }
            #pragma unroll
            for (int mi = 0; mi < MI; mi++)
                #pragma unroll
                for (int ni = 0; ni < NI; ni++)
                    mma_bf16(acc[mi][ni], ah[mi], bh[ni]);
            #pragma unroll
            for (int mi = 0; mi < MI; mi++)
                #pragma unroll
                for (int ni = 0; ni < NI; ni++)
                    mma_bf16(acc[mi][ni], ah[mi], bl[ni]);
            #pragma unroll
            for (int mi = 0; mi < MI; mi++)
                #pragma unroll
                for (int ni = 0; ni < NI; ni++)
                    mma_bf16(acc[mi][ni], al[mi], bh[ni]);
        }
    }

    #pragma unroll
    for (int mi = 0; mi < MI; mi++) {
        #pragma unroll
        for (int ni = 0; ni < NI; ni++) {
            const int r0 = m0 + wm * WM + mi * 16 + (lane >> 2);
            const int cc = n0 + wn * WN + ni * 8 + ((lane & 3) << 1);
            const float b0 = bias[cc], b1 = bias[cc + 1];
            float v0 = acc[mi][ni][0] + b0;
            float v1 = acc[mi][ni][1] + b1;
            float v2 = acc[mi][ni][2] + b0;
            float v3 = acc[mi][ni][3] + b1;
            if (relu) {
                v0 = fmaxf(v0, 0.0f); v1 = fmaxf(v1, 0.0f);
                v2 = fmaxf(v2, 0.0f); v3 = fmaxf(v3, 0.0f);
            }
            if (C) {
                *(float2*)(C + (size_t)r0 * (size_t)ldc + cc)       = make_float2(v0, v1);
                *(float2*)(C + (size_t)(r0 + 8) * (size_t)ldc + cc) = make_float2(v2, v3);
            }
            if (Ohi) {
                __nv_bfloat16 h0, l0, h1, l1, h2, l2, h3, l3;
                split_bf(v0, h0, l0); split_bf(v1, h1, l1);
                split_bf(v2, h2, l2); split_bf(v3, h3, l3);
                *(uint32_t*)(Ohi + (size_t)r0 * ldo + cc) =
                    (uint32_t)__bfloat16_as_ushort(h0) | ((uint32_t)__bfloat16_as_ushort(h1) << 16);
                *(uint32_t*)(Olo + (size_t)r0 * ldo + cc) =
                    (uint32_t)__bfloat16_as_ushort(l0) | ((uint32_t)__bfloat16_as_ushort(l1) << 16);
                *(uint32_t*)(Ohi + (size_t)(r0 + 8) * ldo + cc) =
                    (uint32_t)__bfloat16_as_ushort(h2) | ((uint32_t)__bfloat16_as_ushort(h3) << 16);
                *(uint32_t*)(Olo + (size_t)(r0 + 8) * ldo + cc) =
                    (uint32_t)__bfloat16_as_ushort(l2) | ((uint32_t)__bfloat16_as_ushort(l3) << 16);
            }
        }
    }
}

// chain: 64x64, 4 stages -> 4*20480 = 81920 B (80 KB)
#define SMEM_SMALL (4 * (2 * 64 * 40 * 2 + 2 * 64 * 40 * 2))
// unembed: 128x64, 4 stages -> 4*(2*10240 + 2*5120) = 122880 B (120 KB)
// => exactly 1 unembed CTA/SM, and 120+80 <= 227 KB so a chain CTA co-resides.
#define SMEM_UNE   (4 * (2 * 128 * 40 * 2 + 2 * 64 * 40 * 2))

typedef void (*gemm_small_t)(const __nv_bfloat16*, const __nv_bfloat16*,
                             const __nv_bfloat16*, const __nv_bfloat16*,
                             const float*, float*, long long,
                             __nv_bfloat16*, __nv_bfloat16*, int, int, int);

// ---------------------------------------------------------------------------
// Host orchestration
// ---------------------------------------------------------------------------
extern "C" void kernel_launch(void* const* d_in, const int* in_sizes, int n_in,
                              void* d_out, int out_size) {
    const int*   tok     = (const int*)  d_in[0];
    const float* hidden  = (const float*)d_in[1];
    const float* emb     = (const float*)d_in[2];
    const float* rms_w   = (const float*)d_in[3];
    const float* proj_w  = (const float*)d_in[4];
    const float* proj_b  = (const float*)d_in[5];
    const float* sa_wv   = (const float*)d_in[6];
    const float* sa_bv   = (const float*)d_in[7];
    const float* sa_wo   = (const float*)d_in[8];
    const float* sa_bo   = (const float*)d_in[9];
    const float* ca_wv   = (const float*)d_in[10];
    const float* ca_bv   = (const float*)d_in[11];
    const float* ca_wo   = (const float*)d_in[12];
    const float* ca_bo   = (const float*)d_in[13];
    const float* ln1_w   = (const float*)d_in[14];
    const float* ln1_b   = (const float*)d_in[15];
    const float* ln2_w   = (const float*)d_in[16];
    const float* ln2_b   = (const float*)d_in[17];
    const float* ln3_w   = (const float*)d_in[18];
    const float* ln3_b   = (const float*)d_in[19];
    const float* ff_w1   = (const float*)d_in[20];
    const float* ff_b1   = (const float*)d_in[21];
    const float* ff_w2   = (const float*)d_in[22];
    const float* ff_b2   = (const float*)d_in[23];
    const float* unemb_w = (const float*)d_in[24];
    const float* unemb_b = (const float*)d_in[25];
    float* out = (float*)d_out;

    static __nv_bfloat16 *whi = nullptr, *wlo = nullptr;
    static __nv_bfloat16 *xch = nullptr, *xcl = nullptr;
    static __nv_bfloat16 *xhB = nullptr, *xlB = nullptr;
    static __nv_bfloat16 *t1h = nullptr, *t1l = nullptr;
    static float *x = nullptr, *t2 = nullptr;
    static cudaStream_t s2 = nullptr;
    static cudaEvent_t evStart = nullptr, evDone = nullptr, evH[HH] = {};
    if (!whi) {
        cudaGetSymbolAddress((void**)&whi, g_whi);
        cudaGetSymbolAddress((void**)&wlo, g_wlo);
        cudaGetSymbolAddress((void**)&xch, g_xc_hi);
        cudaGetSymbolAddress((void**)&xcl, g_xc_lo);
        cudaGetSymbolAddress((void**)&xhB, g_x_hi);
        cudaGetSymbolAddress((void**)&xlB, g_x_lo);
        cudaGetSymbolAddress((void**)&t1h, g_t1_hi);
        cudaGetSymbolAddress((void**)&t1l, g_t1_lo);
        cudaGetSymbolAddress((void**)&x,   g_x);
        cudaGetSymbolAddress((void**)&t2,  g_t2);
        cudaFuncSetAttribute((void*)(gemm_small_t)gemm_bf<64, 64, 2, 4, 256, 4>,
                             cudaFuncAttributeMaxDynamicSharedMemorySize, SMEM_SMALL);
        cudaFuncSetAttribute((void*)(gemm_small_t)gemm_bf<128, 64, 2, 4, 256, 4>,
                             cudaFuncAttributeMaxDynamicSharedMemorySize, SMEM_UNE);
        cudaStreamCreateWithFlags(&s2, cudaStreamNonBlocking);
        cudaEventCreateWithFlags(&evStart, cudaEventDisableTiming);
        cudaEventCreateWithFlags(&evDone,  cudaEventDisableTiming);
        for (int i = 0; i < HH; i++) cudaEventCreateWithFlags(&evH[i], cudaEventDisableTiming);
    }

    // fork s2 off the capture stream
    cudaEventRecord(evStart, 0);
    cudaStreamWaitEvent(s2, evStart, 0);

    // unembed weight conversion on s2 (only unembed consumes it)
    conv_w<<<2048, 256, 0, s2>>>(unemb_w, whi + OFF_UNE, wlo + OFF_UNE, 32768000 / 4);

    // chain weight conversions on main stream
    conv_w<<<1024, 256>>>(proj_w,  whi + OFF_PROJ, wlo + OFF_PROJ, 8388608 / 4);
    conv_w<<<1024, 256>>>(sa_wv,   whi + OFF_SAWV, wlo + OFF_SAWV, 4194304 / 4);
    conv_w<<<1024, 256>>>(sa_wo,   whi + OFF_SAWO, wlo + OFF_SAWO, 4194304 / 4);
    conv_w<<<1024, 256>>>(ca_wv,   whi + OFF_CAWV, wlo + OFF_CAWV, 4194304 / 4);
    conv_w<<<1024, 256>>>(ca_wo,   whi + OFF_CAWO, wlo + OFF_CAWO, 4194304 / 4);
    conv_w<<<1024, 256>>>(ff_w1,   whi + OFF_FF1,  wlo + OFF_FF1,  8388608 / 4);
    conv_w<<<1024, 256>>>(ff_w2,   whi + OFF_FF2,  wlo + OFF_FF2,  8388608 / 4);

    init_h_kernel<<<MM, 256>>>(hidden, x);

    for (int h = 0; h < HH; h++) {
        __nv_bfloat16 *XH = xhB + (size_t)h * MM * DD;
        __nv_bfloat16 *XL = xlB + (size_t)h * MM * DD;

        prep_kernel<<<dim3(MM, 2), 256>>>(tok, emb, x, rms_w, xch, xcl, h);

        gemm_bf<64, 64, 2, 4, 256, 4><<<dim3(MM / 64, DD / 64), 256, SMEM_SMALL>>>(
            xch, xcl, whi + OFF_PROJ + (size_t)h * 2097152, wlo + OFF_PROJ + (size_t)h * 2097152,
            proj_b + (size_t)h * DD, x, DD, XH, XL, DD, 2 * DD, 0);

        gemm_bf<64, 64, 2, 4, 256, 4><<<dim3(MM / 64, DD / 64), 256, SMEM_SMALL>>>(
            XH, XL, whi + OFF_SAWV + (size_t)h * 1048576, wlo + OFF_SAWV + (size_t)h * 1048576,
            sa_bv + (size_t)h * DD, nullptr, 0, t1h, t1l, DD, DD, 0);
        gemm_bf<64, 64, 2, 4, 256, 4><<<dim3(MM / 64, DD / 64), 256, SMEM_SMALL>>>(
            t1h, t1l, whi + OFF_SAWO + (size_t)h * 1048576, wlo + OFF_SAWO + (size_t)h * 1048576,
            sa_bo + (size_t)h * DD, t2, DD, nullptr, nullptr, 0, DD, 0);
        resid_ln_kernel<<<MM, 256>>>(x, t2, ln1_w + (size_t)h * DD, ln1_b + (size_t)h * DD, XH, XL);

        gemm_bf<64, 64, 2, 4, 256, 4><<<dim3(MM / 64, DD / 64), 256, SMEM_SMALL>>>(
            XH, XL, whi + OFF_CAWV + (size_t)h * 1048576, wlo + OFF_CAWV + (size_t)h * 1048576,
            ca_bv + (size_t)h * DD, nullptr, 0, t1h, t1l, DD, DD, 0);
        gemm_bf<64, 64, 2, 4, 256, 4><<<dim3(MM / 64, DD / 64), 256, SMEM_SMALL>>>(
            t1h, t1l, whi + OFF_CAWO + (size_t)h * 1048576, wlo + OFF_CAWO + (size_t)h * 1048576,
            ca_bo + (size_t)h * DD, t2, DD, nullptr, nullptr, 0, DD, 0);
        resid_ln_kernel<<<MM, 256>>>(x, t2, ln2_w + (size_t)h * DD, ln2_b + (size_t)h * DD, XH, XL);

        gemm_bf<64, 64, 2, 4, 256, 4><<<dim3(MM / 64, DFF / 64), 256, SMEM_SMALL>>>(
            XH, XL, whi + OFF_FF1 + (size_t)h * 2097152, wlo + OFF_FF1 + (size_t)h * 2097152,
            ff_b1 + (size_t)h * DFF, nullptr, 0, t1h, t1l, DFF, DD, 1);
        gemm_bf<64, 64, 2, 4, 256, 4><<<dim3(MM / 64, DD / 64), 256, SMEM_SMALL>>>(
            t1h, t1l, whi + OFF_FF2 + (size_t)h * 2097152, wlo + OFF_FF2 + (size_t)h * 2097152,
            ff_b2 + (size_t)h * DD, t2, DD, nullptr, nullptr, 0, DFF, 0);
        resid_ln_kernel<<<MM, 256>>>(x, t2, ln3_w + (size_t)h * DD, ln3_b + (size_t)h * DD, XH, XL);

        // hand final activations of head h to stream s2 for the unembed GEMM
        cudaEventRecord(evH[h], 0);
        cudaStreamWaitEvent(s2, evH[h], 0);
        gemm_bf<128, 64, 2, 4, 256, 4><<<dim3(MM / 128, VV / 64), 256, SMEM_UNE, s2>>>(
            XH, XL, whi + OFF_UNE, wlo + OFF_UNE,
            unemb_b, out + (size_t)h * VV, (long long)HH * VV, nullptr, nullptr, 0, DD, 0);
    }

    // join s2 back into the capture stream
    cudaEventRecord(evDone, s2);
    cudaStreamWaitEvent(0, evDone, 0);
}

// round 11
// speedup vs baseline: 1.1702x; 1.1702x over previous
#include <cuda_runtime.h>
#include <cuda_bf16.h>
#include <cstdint>

// Problem constants
#define BB   2
#define TT   260
#define HH   4
#define DD   1024
#define VV   32000
#define DFF  2048
#define MM   512

// ---------------------------------------------------------------------------
// Persistent scratch (__device__ globals; no allocations allowed)
// ---------------------------------------------------------------------------
#define OFF_PROJ 0
#define OFF_SAWV 8388608
#define OFF_SAWO 12582912
#define OFF_CAWV 16777216
#define OFF_CAWO 20971520
#define OFF_FF1  25165824
#define OFF_FF2  33554432
#define OFF_UNE  41943040
#define W_TOTAL  74711040

__device__ __nv_bfloat16 g_whi[W_TOTAL];
__device__ __nv_bfloat16 g_wlo[W_TOTAL];

__device__ float g_x  [MM * DD];
__device__ float g_t2 [MM * DD];
__device__ __nv_bfloat16 g_xc_hi[MM * 2 * DD], g_xc_lo[MM * 2 * DD];
__device__ __nv_bfloat16 g_x_hi [HH][MM * DD], g_x_lo [HH][MM * DD]; // per-head
__device__ __nv_bfloat16 g_t1_hi[MM * DFF],    g_t1_lo[MM * DFF];

// ---------------------------------------------------------------------------
// helpers
// ---------------------------------------------------------------------------
__device__ __forceinline__ float block_sum(float v) {
    __shared__ float sh[32];
    const int lane = threadIdx.x & 31;
    const int wid  = threadIdx.x >> 5;
    #pragma unroll
    for (int o = 16; o; o >>= 1) v += __shfl_xor_sync(0xffffffffu, v, o);
    if (lane == 0) sh[wid] = v;
    __syncthreads();
    if (wid == 0) {
        v = (lane < 8) ? sh[lane] : 0.0f;
        #pragma unroll
        for (int o = 4; o; o >>= 1) v += __shfl_xor_sync(0xffffffffu, v, o);
        if (lane == 0) sh[0] = v;
    }
    __syncthreads();
    v = sh[0];
    __syncthreads();
    return v;
}

__device__ __forceinline__ uint32_t s2u(const void* p) {
    uint32_t a;
    asm("{ .reg .u64 t; cvta.to.shared.u64 t, %1; cvt.u32.u64 %0, t; }" : "=r"(a) : "l"(p));
    return a;
}
__device__ __forceinline__ void ldsm4(uint32_t* r, uint32_t addr) {
    asm volatile("ldmatrix.sync.aligned.m8n8.x4.shared.b16 {%0,%1,%2,%3}, [%4];"
                 : "=r"(r[0]), "=r"(r[1]), "=r"(r[2]), "=r"(r[3]) : "r"(addr));
}
__device__ __forceinline__ void mma_bf16(float* c, const uint32_t* a, const uint32_t* b) {
    asm volatile(
        "mma.sync.aligned.m16n8k16.row.col.f32.bf16.bf16.f32 "
        "{%0,%1,%2,%3}, {%4,%5,%6,%7}, {%8,%9}, {%0,%1,%2,%3};"
        : "+f"(c[0]), "+f"(c[1]), "+f"(c[2]), "+f"(c[3])
        : "r"(a[0]), "r"(a[1]), "r"(a[2]), "r"(a[3]), "r"(b[0]), "r"(b[1]));
}
__device__ __forceinline__ void split_bf(float f, __nv_bfloat16& h, __nv_bfloat16& l) {
    h = __float2bfloat16_rn(f);
    l = __float2bfloat16_rn(f - __bfloat162float(h));
}

// ---------------------------------------------------------------------------
// weight conversion: fp32 -> bf16 hi/lo
// ---------------------------------------------------------------------------
__global__ void conv_w(const float* __restrict__ src,
                       __nv_bfloat16* __restrict__ hi,
                       __nv_bfloat16* __restrict__ lo, int n4) {
    int i = blockIdx.x * blockDim.x + threadIdx.x;
    const int stride = gridDim.x * blockDim.x;
    for (; i < n4; i += stride) {
        float4 v = ((const float4*)src)[i];
        float f[4] = { v.x, v.y, v.z, v.w };
        uint32_t hp[2], lp[2];
        #pragma unroll
        for (int q = 0; q < 2; q++) {
            __nv_bfloat16 h0, l0, h1, l1;
            split_bf(f[2*q],   h0, l0);
            split_bf(f[2*q+1], h1, l1);
            hp[q] = (uint32_t)__bfloat16_as_ushort(h0) | ((uint32_t)__bfloat16_as_ushort(h1) << 16);
            lp[q] = (uint32_t)__bfloat16_as_ushort(l0) | ((uint32_t)__bfloat16_as_ushort(l1) << 16);
        }
        ((uint2*)hi)[i] = make_uint2(hp[0], hp[1]);
        ((uint2*)lo)[i] = make_uint2(lp[0], lp[1]);
    }
}

__global__ void init_h_kernel(const float* __restrict__ hidden, float* __restrict__ hbuf) {
    const int m = blockIdx.x;
    const int b = m >> 8, j = m & 255;
    const float* src = hidden + ((size_t)b * TT + j) * DD;
    float* dst = hbuf + (size_t)m * DD;
    #pragma unroll
    for (int i = 0; i < 4; i++) dst[threadIdx.x + i * 256] = src[threadIdx.x + i * 256];
}

__global__ void prep_kernel(const int* __restrict__ tok,
                            const float* __restrict__ emb,
                            const float* __restrict__ hprev,
                            const float* __restrict__ rms_w,
                            __nv_bfloat16* __restrict__ xch,
                            __nv_bfloat16* __restrict__ xcl, int h) {
    const int m = blockIdx.x;
    const int half = blockIdx.y;
    const int tid = threadIdx.x;
    const int b = m >> 8, j = m & 255;
    const float* src;
    if (half == 0) {
        const int t = tok[b * TT + 1 + h + j];
        src = emb + (size_t)t * DD;
    } else {
        src = hprev + (size_t)m * DD;
    }
    float v[4];
    float ss = 0.0f;
    #pragma unroll
    for (int i = 0; i < 4; i++) { v[i] = src[tid + i * 256]; ss += v[i] * v[i]; }
    ss = block_sum(ss);
    const float s = rsqrtf(ss * (1.0f / DD) + 1e-6f);
    const size_t base = (size_t)m * (2 * DD) + half * DD;
    #pragma unroll
    for (int i = 0; i < 4; i++) {
        const int d = tid + i * 256;
        const float f = v[i] * s * rms_w[d];
        __nv_bfloat16 hh, ll;
        split_bf(f, hh, ll);
        xch[base + d] = hh;
        xcl[base + d] = ll;
    }
}

__global__ void resid_ln_kernel(float* __restrict__ x, const float* __restrict__ u,
                                const float* __restrict__ w, const float* __restrict__ bb,
                                __nv_bfloat16* __restrict__ oh, __nv_bfloat16* __restrict__ ol) {
    const int m = blockIdx.x;
    const int tid = threadIdx.x;
    float* xr = x + (size_t)m * DD;
    const float* ur = u + (size_t)m * DD;
    float v[4];
    float s = 0.0f;
    #pragma unroll
    for (int i = 0; i < 4; i++) {
        v[i] = xr[tid + i * 256] + ur[tid + i * 256];
        s += v[i];
    }
    s = block_sum(s);
    const float mu = s * (1.0f / DD);
    float s2 = 0.0f;
    #pragma unroll
    for (int i = 0; i < 4; i++) { const float d = v[i] - mu; s2 += d * d; }
    s2 = block_sum(s2);
    const float rs = rsqrtf(s2 * (1.0f / DD) + 1e-5f);
    #pragma unroll
    for (int i = 0; i < 4; i++) {
        const int d = tid + i * 256;
        const float f = (v[i] - mu) * rs * w[d] + bb[d];
        xr[d] = f;
        __nv_bfloat16 hh, ll;
        split_bf(f, hh, ll);
        oh[(size_t)m * DD + d] = hh;
        ol[(size_t)m * DD + d] = ll;
    }
}

// ---------------------------------------------------------------------------
// bf16 split-precision GEMM (3-product emulation), cp.async S-stage pipeline.
// ---------------------------------------------------------------------------
template<int BM, int BN, int WGM, int WGN, int NTH, int S>
__global__ void __launch_bounds__(NTH) gemm_bf(
    const __nv_bfloat16* __restrict__ Ahi, const __nv_bfloat16* __restrict__ Alo,
    const __nv_bfloat16* __restrict__ Bhi, const __nv_bfloat16* __restrict__ Blo,
    const float* __restrict__ bias,
    float* __restrict__ C, long long ldc,
    __nv_bfloat16* __restrict__ Ohi, __nv_bfloat16* __restrict__ Olo, int ldo,
    int K, int relu)
{
    constexpr int WM  = BM / WGM;
    constexpr int WN  = BN / WGN;
    constexpr int MI  = WM / 16;
    constexpr int NI  = WN / 8;
    constexpr int LS  = 40;
    constexpr int AT  = BM * LS * 2;
    constexpr int BT  = BN * LS * 2;
    constexpr int STAGE = 2 * AT + 2 * BT;

    extern __shared__ char smem[];
    const uint32_t sb = s2u(smem);

    const int tid  = threadIdx.x;
    const int wid  = tid >> 5;
    const int lane = tid & 31;
    const int wm   = wid / WGN;
    const int wn   = wid % WGN;
    const int m0   = blockIdx.x * BM;
    const int n0   = blockIdx.y * BN;
    const int nCh  = K >> 5;

    float acc[MI][NI][4];
    #pragma unroll
    for (int i = 0; i < MI; i++)
        #pragma unroll
        for (int j = 0; j < NI; j++)
            #pragma unroll
            for (int q = 0; q < 4; q++) acc[i][j][q] = 0.0f;

    auto issue = [&](int c) {
        if (c < nCh) {
            const int k0 = c << 5;
            const uint32_t st = sb + (uint32_t)(c % S) * STAGE;
            #pragma unroll
            for (int q = tid; q < BM * 4; q += NTH) {
                const int row = q >> 2, col = (q & 3) << 3;
                const size_t off = (size_t)(m0 + row) * K + k0 + col;
                const uint32_t d = st + (uint32_t)(row * LS + col) * 2u;
                asm volatile("cp.async.cg.shared.global [%0], [%1], 16;" :: "r"(d), "l"(Ahi + off));
                asm volatile("cp.async.cg.shared.global [%0], [%1], 16;" :: "r"(d + AT), "l"(Alo + off));
            }
            #pragma unroll
            for (int q = tid; q < BN * 4; q += NTH) {
                const int row = q >> 2, col = (q & 3) << 3;
                const size_t off = (size_t)(n0 + row) * K + k0 + col;
                const uint32_t d = st + 2 * AT + (uint32_t)(row * LS + col) * 2u;
                asm volatile("cp.async.cg.shared.global [%0], [%1], 16;" :: "r"(d), "l"(Bhi + off));
                asm volatile("cp.async.cg.shared.global [%0], [%1], 16;" :: "r"(d + BT), "l"(Blo + off));
            }
        }
        asm volatile("cp.async.commit_group;" ::: "memory");
    };

    #pragma unroll
    for (int p = 0; p < S - 1; p++) issue(p);

    for (int c = 0; c < nCh; c++) {
        asm volatile("cp.async.wait_group %0;" :: "n"(S - 2) : "memory");
        __syncthreads();
        issue(c + S - 1);

        const uint32_t st  = sb + (uint32_t)(c % S) * STAGE;
        const uint32_t sAh = st;
        const uint32_t sBh = st + 2 * AT;
        #pragma unroll
        for (int ks = 0; ks < 2; ks++) {
            uint32_t ah[MI][4], al[MI][4];
            #pragma unroll
            for (int mi = 0; mi < MI; mi++) {
                const int row = wm * WM + mi * 16 + (lane & 15);
                const int col = ks * 16 + (lane >> 4) * 8;
                const uint32_t ad = sAh + (uint32_t)(row * LS + col) * 2u;
                ldsm4(ah[mi], ad);
                ldsm4(al[mi], ad + AT);
            }
            uint32_t bh[NI][2], bl[NI][2];
            #pragma unroll
            for (int ni = 0; ni < NI; ni += 2) {
                const int g = lane >> 3;
                const int row = wn * WN + ni * 8 + ((g >> 1) << 3) + (lane & 7);
                const int col = ks * 16 + ((g & 1) << 3);
                const uint32_t bd = sBh + (uint32_t)(row * LS + col) * 2u;
                ldsm4(&bh[ni][0], bd);
                ldsm4(&bl[ni][0], bd + BT);
            }
            #pragma unroll
            for (int mi = 0; mi < MI; mi++)
                #pragma unroll
                for (int ni = 0; ni < NI; ni++)
                    mma_bf16(acc[mi][ni], ah[mi], bh[ni]);
            #pragma unroll
            for (int mi = 0; mi < MI; mi++)
                #pragma unroll
                for (int ni = 0; ni < NI; ni++)
                    mma_bf16(acc[mi][ni], ah[mi], bl[ni]);
            #pragma unroll
            for (int mi = 0; mi < MI; mi++)
                #pragma unroll
                for (int ni = 0; ni < NI; ni++)
                    mma_bf16(acc[mi][ni], al[mi], bh[ni]);
        }
    }

    #pragma unroll
    for (int mi = 0; mi < MI; mi++) {
        #pragma unroll
        for (int ni = 0; ni < NI; ni++) {
            const int r0 = m0 + wm * WM + mi * 16 + (lane >> 2);
            const int cc = n0 + wn * WN + ni * 8 + ((lane & 3) << 1);
            const float b0 = bias[cc], b1 = bias[cc + 1];
            float v0 = acc[mi][ni][0] + b0;
            float v1 = acc[mi][ni][1] + b1;
            float v2 = acc[mi][ni][2] + b0;
            float v3 = acc[mi][ni][3] + b1;
            if (relu) {
                v0 = fmaxf(v0, 0.0f); v1 = fmaxf(v1, 0.0f);
                v2 = fmaxf(v2, 0.0f); v3 = fmaxf(v3, 0.0f);
            }
            if (C) {
                *(float2*)(C + (size_t)r0 * (size_t)ldc + cc)       = make_float2(v0, v1);
                *(float2*)(C + (size_t)(r0 + 8) * (size_t)ldc + cc) = make_float2(v2, v3);
            }
            if (Ohi) {
                __nv_bfloat16 h0, l0, h1, l1, h2, l2, h3, l3;
                split_bf(v0, h0, l0); split_bf(v1, h1, l1);
                split_bf(v2, h2, l2); split_bf(v3, h3, l3);
                *(uint32_t*)(Ohi + (size_t)r0 * ldo + cc) =
                    (uint32_t)__bfloat16_as_ushort(h0) | ((uint32_t)__bfloat16_as_ushort(h1) << 16);
                *(uint32_t*)(Olo + (size_t)r0 * ldo + cc) =
                    (uint32_t)__bfloat16_as_ushort(l0) | ((uint32_t)__bfloat16_as_ushort(l1) << 16);
                *(uint32_t*)(Ohi + (size_t)(r0 + 8) * ldo + cc) =
                    (uint32_t)__bfloat16_as_ushort(h2) | ((uint32_t)__bfloat16_as_ushort(h3) << 16);
                *(uint32_t*)(Olo + (size_t)(r0 + 8) * ldo + cc) =
                    (uint32_t)__bfloat16_as_ushort(l2) | ((uint32_t)__bfloat16_as_ushort(l3) << 16);
            }
        }
    }
}

// chain: 64x64, 3 stages -> 61440 B (60 KB)
#define SMEM_SMALL (3 * (2 * 64 * 40 * 2 + 2 * 64 * 40 * 2))
// unembed: 128x128, 3 stages -> 3*40960 = 122880 B (120 KB)
// co-residency per SM: smem 120+60=180 <= 227 KB, regs ~30K+~19K <= 64K,
// threads 256+256, and 2 unembed CTAs cannot pack (240 > 227).
#define SMEM_UNE   (3 * (2 * 128 * 40 * 2 + 2 * 128 * 40 * 2))

typedef void (*gemm_small_t)(const __nv_bfloat16*, const __nv_bfloat16*,
                             const __nv_bfloat16*, const __nv_bfloat16*,
                             const float*, float*, long long,
                             __nv_bfloat16*, __nv_bfloat16*, int, int, int);

// ---------------------------------------------------------------------------
// Host orchestration
// ---------------------------------------------------------------------------
extern "C" void kernel_launch(void* const* d_in, const int* in_sizes, int n_in,
                              void* d_out, int out_size) {
    const int*   tok     = (const int*)  d_in[0];
    const float* hidden  = (const float*)d_in[1];
    const float* emb     = (const float*)d_in[2];
    const float* rms_w   = (const float*)d_in[3];
    const float* proj_w  = (const float*)d_in[4];
    const float* proj_b  = (const float*)d_in[5];
    const float* sa_wv   = (const float*)d_in[6];
    const float* sa_bv   = (const float*)d_in[7];
    const float* sa_wo   = (const float*)d_in[8];
    const float* sa_bo   = (const float*)d_in[9];
    const float* ca_wv   = (const float*)d_in[10];
    const float* ca_bv   = (const float*)d_in[11];
    const float* ca_wo   = (const float*)d_in[12];
    const float* ca_bo   = (const float*)d_in[13];
    const float* ln1_w   = (const float*)d_in[14];
    const float* ln1_b   = (const float*)d_in[15];
    const float* ln2_w   = (const float*)d_in[16];
    const float* ln2_b   = (const float*)d_in[17];
    const float* ln3_w   = (const float*)d_in[18];
    const float* ln3_b   = (const float*)d_in[19];
    const float* ff_w1   = (const float*)d_in[20];
    const float* ff_b1   = (const float*)d_in[21];
    const float* ff_w2   = (const float*)d_in[22];
    const float* ff_b2   = (const float*)d_in[23];
    const float* unemb_w = (const float*)d_in[24];
    const float* unemb_b = (const float*)d_in[25];
    float* out = (float*)d_out;

    static __nv_bfloat16 *whi = nullptr, *wlo = nullptr;
    static __nv_bfloat16 *xch = nullptr, *xcl = nullptr;
    static __nv_bfloat16 *xhB = nullptr, *xlB = nullptr;
    static __nv_bfloat16 *t1h = nullptr, *t1l = nullptr;
    static float *x = nullptr, *t2 = nullptr;
    static cudaStream_t s2 = nullptr;
    static cudaEvent_t evStart = nullptr, evDone = nullptr, evH[HH] = {};
    if (!whi) {
        cudaGetSymbolAddress((void**)&whi, g_whi);
        cudaGetSymbolAddress((void**)&wlo, g_wlo);
        cudaGetSymbolAddress((void**)&xch, g_xc_hi);
        cudaGetSymbolAddress((void**)&xcl, g_xc_lo);
        cudaGetSymbolAddress((void**)&xhB, g_x_hi);
        cudaGetSymbolAddress((void**)&xlB, g_x_lo);
        cudaGetSymbolAddress((void**)&t1h, g_t1_hi);
        cudaGetSymbolAddress((void**)&t1l, g_t1_lo);
        cudaGetSymbolAddress((void**)&x,   g_x);
        cudaGetSymbolAddress((void**)&t2,  g_t2);
        cudaFuncSetAttribute((void*)(gemm_small_t)gemm_bf<64, 64, 2, 4, 256, 3>,
                             cudaFuncAttributeMaxDynamicSharedMemorySize, SMEM_SMALL);
        cudaFuncSetAttribute((void*)(gemm_small_t)gemm_bf<128, 128, 2, 4, 256, 3>,
                             cudaFuncAttributeMaxDynamicSharedMemorySize, SMEM_UNE);
        cudaStreamCreateWithFlags(&s2, cudaStreamNonBlocking);
        cudaEventCreateWithFlags(&evStart, cudaEventDisableTiming);
        cudaEventCreateWithFlags(&evDone,  cudaEventDisableTiming);
        for (int i = 0; i < HH; i++) cudaEventCreateWithFlags(&evH[i], cudaEventDisableTiming);
    }

    // fork s2 off the capture stream
    cudaEventRecord(evStart, 0);
    cudaStreamWaitEvent(s2, evStart, 0);

    // unembed weight conversion on s2 (only unembed consumes it)
    conv_w<<<2048, 256, 0, s2>>>(unemb_w, whi + OFF_UNE, wlo + OFF_UNE, 32768000 / 4);

    // chain weight conversions on main stream
    conv_w<<<1024, 256>>>(proj_w,  whi + OFF_PROJ, wlo + OFF_PROJ, 8388608 / 4);
    conv_w<<<1024, 256>>>(sa_wv,   whi + OFF_SAWV, wlo + OFF_SAWV, 4194304 / 4);
    conv_w<<<1024, 256>>>(sa_wo,   whi + OFF_SAWO, wlo + OFF_SAWO, 4194304 / 4);
    conv_w<<<1024, 256>>>(ca_wv,   whi + OFF_CAWV, wlo + OFF_CAWV, 4194304 / 4);
    conv_w<<<1024, 256>>>(ca_wo,   whi + OFF_CAWO, wlo + OFF_CAWO, 4194304 / 4);
    conv_w<<<1024, 256>>>(ff_w1,   whi + OFF_FF1,  wlo + OFF_FF1,  8388608 / 4);
    conv_w<<<1024, 256>>>(ff_w2,   whi + OFF_FF2,  wlo + OFF_FF2,  8388608 / 4);

    init_h_kernel<<<MM, 256>>>(hidden, x);

    for (int h = 0; h < HH; h++) {
        __nv_bfloat16 *XH = xhB + (size_t)h * MM * DD;
        __nv_bfloat16 *XL = xlB + (size_t)h * MM * DD;

        prep_kernel<<<dim3(MM, 2), 256>>>(tok, emb, x, rms_w, xch, xcl, h);

        gemm_bf<64, 64, 2, 4, 256, 3><<<dim3(MM / 64, DD / 64), 256, SMEM_SMALL>>>(
            xch, xcl, whi + OFF_PROJ + (size_t)h * 2097152, wlo + OFF_PROJ + (size_t)h * 2097152,
            proj_b + (size_t)h * DD, x, DD, XH, XL, DD, 2 * DD, 0);

        gemm_bf<64, 64, 2, 4, 256, 3><<<dim3(MM / 64, DD / 64), 256, SMEM_SMALL>>>(
            XH, XL, whi + OFF_SAWV + (size_t)h * 1048576, wlo + OFF_SAWV + (size_t)h * 1048576,
            sa_bv + (size_t)h * DD, nullptr, 0, t1h, t1l, DD, DD, 0);
        gemm_bf<64, 64, 2, 4, 256, 3><<<dim3(MM / 64, DD / 64), 256, SMEM_SMALL>>>(
            t1h, t1l, whi + OFF_SAWO + (size_t)h * 1048576, wlo + OFF_SAWO + (size_t)h * 1048576,
            sa_bo + (size_t)h * DD, t2, DD, nullptr, nullptr, 0, DD, 0);
        resid_ln_kernel<<<MM, 256>>>(x, t2, ln1_w + (size_t)h * DD, ln1_b + (size_t)h * DD, XH, XL);

        gemm_bf<64, 64, 2, 4, 256, 3><<<dim3(MM / 64, DD / 64), 256, SMEM_SMALL>>>(
            XH, XL, whi + OFF_CAWV + (size_t)h * 1048576, wlo + OFF_CAWV + (size_t)h * 1048576,
            ca_bv + (size_t)h * DD, nullptr, 0, t1h, t1l, DD, DD, 0);
        gemm_bf<64, 64, 2, 4, 256, 3><<<dim3(MM / 64, DD / 64), 256, SMEM_SMALL>>>(
            t1h, t1l, whi + OFF_CAWO + (size_t)h * 1048576, wlo + OFF_CAWO + (size_t)h * 1048576,
            ca_bo + (size_t)h * DD, t2, DD, nullptr, nullptr, 0, DD, 0);
        resid_ln_kernel<<<MM, 256>>>(x, t2, ln2_w + (size_t)h * DD, ln2_b + (size_t)h * DD, XH, XL);

        gemm_bf<64, 64, 2, 4, 256, 3><<<dim3(MM / 64, DFF / 64), 256, SMEM_SMALL>>>(
            XH, XL, whi + OFF_FF1 + (size_t)h * 2097152, wlo + OFF_FF1 + (size_t)h * 2097152,
            ff_b1 + (size_t)h * DFF, nullptr, 0, t1h, t1l, DFF, DD, 1);
        gemm_bf<64, 64, 2, 4, 256, 3><<<dim3(MM / 64, DD / 64), 256, SMEM_SMALL>>>(
            t1h, t1l, whi + OFF_FF2 + (size_t)h * 2097152, wlo + OFF_FF2 + (size_t)h * 2097152,
            ff_b2 + (size_t)h * DD, t2, DD, nullptr, nullptr, 0, DFF, 0);
        resid_ln_kernel<<<MM, 256>>>(x, t2, ln3_w + (size_t)h * DD, ln3_b + (size_t)h * DD, XH, XL);

        // hand final activations of head h to stream s2 for the unembed GEMM
        cudaEventRecord(evH[h], 0);
        cudaStreamWaitEvent(s2, evH[h], 0);
        gemm_bf<128, 128, 2, 4, 256, 3><<<dim3(MM / 128, VV / 128), 256, SMEM_UNE, s2>>>(
            XH, XL, whi + OFF_UNE, wlo + OFF_UNE,
            unemb_b, out + (size_t)h * VV, (long long)HH * VV, nullptr, nullptr, 0, DD, 0);
    }

    // join s2 back into the capture stream
    cudaEventRecord(evDone, s2);
    cudaStreamWaitEvent(0, evDone, 0);
}

// round 13
// speedup vs baseline: 1.9893x; 1.7000x over previous
#include <cuda_runtime.h>
#include <cuda_fp16.h>
#include <cstdint>

// Problem constants
#define BB   2
#define TT   260
#define HH   4
#define DD   1024
#define VV   32000
#define DFF  2048
#define MM   512

// ---------------------------------------------------------------------------
// Persistent scratch (__device__ globals; no allocations allowed)
// ---------------------------------------------------------------------------
#define OFF_PROJ 0
#define OFF_SAWV 8388608
#define OFF_SAWO 12582912
#define OFF_CAWV 16777216
#define OFF_CAWO 20971520
#define OFF_FF1  25165824
#define OFF_FF2  33554432
#define OFF_UNE  41943040
#define W_TOTAL  74711040

__device__ __half g_wh[W_TOTAL];                 // single-fp16 weights

__device__ float g_x  [MM * DD];
__device__ float g_t2 [MM * DD];
__device__ __half g_xc_hi[MM * 2 * DD], g_xc_lo[MM * 2 * DD];
__device__ __half g_x_hi [HH][MM * DD], g_x_lo [HH][MM * DD];  // per-head
__device__ __half g_t1_hi[MM * DFF],    g_t1_lo[MM * DFF];

// ---------------------------------------------------------------------------
// helpers
// ---------------------------------------------------------------------------
__device__ __forceinline__ float block_sum(float v) {
    __shared__ float sh[32];
    const int lane = threadIdx.x & 31;
    const int wid  = threadIdx.x >> 5;
    #pragma unroll
    for (int o = 16; o; o >>= 1) v += __shfl_xor_sync(0xffffffffu, v, o);
    if (lane == 0) sh[wid] = v;
    __syncthreads();
    if (wid == 0) {
        v = (lane < 8) ? sh[lane] : 0.0f;
        #pragma unroll
        for (int o = 4; o; o >>= 1) v += __shfl_xor_sync(0xffffffffu, v, o);
        if (lane == 0) sh[0] = v;
    }
    __syncthreads();
    v = sh[0];
    __syncthreads();
    return v;
}

__device__ __forceinline__ uint32_t s2u(const void* p) {
    uint32_t a;
    asm("{ .reg .u64 t; cvta.to.shared.u64 t, %1; cvt.u32.u64 %0, t; }" : "=r"(a) : "l"(p));
    return a;
}
__device__ __forceinline__ void ldsm4(uint32_t* r, uint32_t addr) {
    asm volatile("ldmatrix.sync.aligned.m8n8.x4.shared.b16 {%0,%1,%2,%3}, [%4];"
                 : "=r"(r[0]), "=r"(r[1]), "=r"(r[2]), "=r"(r[3]) : "r"(addr));
}
__device__ __forceinline__ void mma_f16(float* c, const uint32_t* a, const uint32_t* b) {
    asm volatile(
        "mma.sync.aligned.m16n8k16.row.col.f32.f16.f16.f32 "
        "{%0,%1,%2,%3}, {%4,%5,%6,%7}, {%8,%9}, {%0,%1,%2,%3};"
        : "+f"(c[0]), "+f"(c[1]), "+f"(c[2]), "+f"(c[3])
        : "r"(a[0]), "r"(a[1]), "r"(a[2]), "r"(a[3]), "r"(b[0]), "r"(b[1]));
}
__device__ __forceinline__ void split_h(float f, __half& h, __half& l) {
    h = __float2half_rn(f);
    l = __float2half_rn(f - __half2float(h));
}
__device__ __forceinline__ uint32_t pack_h2(__half a, __half b) {
    __half2 p = __halves2half2(a, b);
    return *reinterpret_cast<uint32_t*>(&p);
}

// ---------------------------------------------------------------------------
// weight conversion: fp32 -> single fp16
// ---------------------------------------------------------------------------
__global__ void conv_w(const float* __restrict__ src, __half* __restrict__ dst, int n4) {
    int i = blockIdx.x * blockDim.x + threadIdx.x;
    const int stride = gridDim.x * blockDim.x;
    for (; i < n4; i += stride) {
        float4 v = ((const float4*)src)[i];
        uint32_t p0 = pack_h2(__float2half_rn(v.x), __float2half_rn(v.y));
        uint32_t p1 = pack_h2(__float2half_rn(v.z), __float2half_rn(v.w));
        ((uint2*)dst)[i] = make_uint2(p0, p1);
    }
}

__global__ void init_h_kernel(const float* __restrict__ hidden, float* __restrict__ hbuf) {
    const int m = blockIdx.x;
    const int b = m >> 8, j = m & 255;
    const float* src = hidden + ((size_t)b * TT + j) * DD;
    float* dst = hbuf + (size_t)m * DD;
    #pragma unroll
    for (int i = 0; i < 4; i++) dst[threadIdx.x + i * 256] = src[threadIdx.x + i * 256];
}

__global__ void prep_kernel(const int* __restrict__ tok,
                            const float* __restrict__ emb,
                            const float* __restrict__ hprev,
                            const float* __restrict__ rms_w,
                            __half* __restrict__ xch,
                            __half* __restrict__ xcl, int h) {
    const int m = blockIdx.x;
    const int half = blockIdx.y;
    const int tid = threadIdx.x;
    const int b = m >> 8, j = m & 255;
    const float* src;
    if (half == 0) {
        const int t = tok[b * TT + 1 + h + j];
        src = emb + (size_t)t * DD;
    } else {
        src = hprev + (size_t)m * DD;
    }
    float v[4];
    float ss = 0.0f;
    #pragma unroll
    for (int i = 0; i < 4; i++) { v[i] = src[tid + i * 256]; ss += v[i] * v[i]; }
    ss = block_sum(ss);
    const float s = rsqrtf(ss * (1.0f / DD) + 1e-6f);
    const size_t base = (size_t)m * (2 * DD) + half * DD;
    #pragma unroll
    for (int i = 0; i < 4; i++) {
        const int d = tid + i * 256;
        const float f = v[i] * s * rms_w[d];
        __half hh, ll;
        split_h(f, hh, ll);
        xch[base + d] = hh;
        xcl[base + d] = ll;
    }
}

__global__ void resid_ln_kernel(float* __restrict__ x, const float* __restrict__ u,
                                const float* __restrict__ w, const float* __restrict__ bb,
                                __half* __restrict__ oh, __half* __restrict__ ol) {
    const int m = blockIdx.x;
    const int tid = threadIdx.x;
    float* xr = x + (size_t)m * DD;
    const float* ur = u + (size_t)m * DD;
    float v[4];
    float s = 0.0f;
    #pragma unroll
    for (int i = 0; i < 4; i++) {
        v[i] = xr[tid + i * 256] + ur[tid + i * 256];
        s += v[i];
    }
    s = block_sum(s);
    const float mu = s * (1.0f / DD);
    float s2 = 0.0f;
    #pragma unroll
    for (int i = 0; i < 4; i++) { const float d = v[i] - mu; s2 += d * d; }
    s2 = block_sum(s2);
    const float rs = rsqrtf(s2 * (1.0f / DD) + 1e-5f);
    #pragma unroll
    for (int i = 0; i < 4; i++) {
        const int d = tid + i * 256;
        const float f = (v[i] - mu) * rs * w[d] + bb[d];
        xr[d] = f;
        __half hh, ll;
        split_h(f, hh, ll);
        oh[(size_t)m * DD + d] = hh;
        ol[(size_t)m * DD + d] = ll;
    }
}

// ---------------------------------------------------------------------------
// fp16 GEMM: C[m,n] = sum_k A[m,k]*B[n,k] + bias[n]
// NPROD=2: A = (Ahi + Alo) fp16 hi/lo pair   (chain: x to ~2^-23 precision)
// NPROD=1: A = Ahi only                      (unembed)
// B: single fp16. cp.async S-stage pipeline, LS=40-elem padded rows.
// ---------------------------------------------------------------------------
template<int BM, int BN, int WGM, int WGN, int NTH, int S, int NPROD>
__global__ void __launch_bounds__(NTH) gemm_fp16(
    const __half* __restrict__ Ahi, const __half* __restrict__ Alo,
    const __half* __restrict__ Bh,
    const float* __restrict__ bias,
    float* __restrict__ C, long long ldc,
    __half* __restrict__ Ohi, __half* __restrict__ Olo, int ldo,
    int K, int relu)
{
    constexpr int WM  = BM / WGM;
    constexpr int WN  = BN / WGN;
    constexpr int MI  = WM / 16;
    constexpr int NI  = WN / 8;
    constexpr int LS  = 40;
    constexpr int AT  = BM * LS * 2;
    constexpr int BT  = BN * LS * 2;
    constexpr int STAGE = NPROD * AT + BT;

    extern __shared__ char smem[];
    const uint32_t sb = s2u(smem);

    const int tid  = threadIdx.x;
    const int wid  = tid >> 5;
    const int lane = tid & 31;
    const int wm   = wid / WGN;
    const int wn   = wid % WGN;
    const int m0   = blockIdx.x * BM;
    const int n0   = blockIdx.y * BN;
    const int nCh  = K >> 5;

    float acc[MI][NI][4];
    #pragma unroll
    for (int i = 0; i < MI; i++)
        #pragma unroll
        for (int j = 0; j < NI; j++)
            #pragma unroll
            for (int q = 0; q < 4; q++) acc[i][j][q] = 0.0f;

    auto issue = [&](int c) {
        if (c < nCh) {
            const int k0 = c << 5;
            const uint32_t st = sb + (uint32_t)(c % S) * STAGE;
            #pragma unroll
            for (int q = tid; q < BM * 4; q += NTH) {
                const int row = q >> 2, col = (q & 3) << 3;
                const size_t off = (size_t)(m0 + row) * K + k0 + col;
                const uint32_t d = st + (uint32_t)(row * LS + col) * 2u;
                asm volatile("cp.async.cg.shared.global [%0], [%1], 16;" :: "r"(d), "l"(Ahi + off));
                if (NPROD == 2)
                    asm volatile("cp.async.cg.shared.global [%0], [%1], 16;" :: "r"(d + AT), "l"(Alo + off));
            }
            #pragma unroll
            for (int q = tid; q < BN * 4; q += NTH) {
                const int row = q >> 2, col = (q & 3) << 3;
                const size_t off = (size_t)(n0 + row) * K + k0 + col;
                const uint32_t d = st + NPROD * AT + (uint32_t)(row * LS + col) * 2u;
                asm volatile("cp.async.cg.shared.global [%0], [%1], 16;" :: "r"(d), "l"(Bh + off));
            }
        }
        asm volatile("cp.async.commit_group;" ::: "memory");
    };

    #pragma unroll
    for (int p = 0; p < S - 1; p++) issue(p);

    for (int c = 0; c < nCh; c++) {
        asm volatile("cp.async.wait_group %0;" :: "n"(S - 2) : "memory");
        __syncthreads();
        issue(c + S - 1);

        const uint32_t st  = sb + (uint32_t)(c % S) * STAGE;
        const uint32_t sAh = st;
        const uint32_t sBh = st + NPROD * AT;
        #pragma unroll
        for (int ks = 0; ks < 2; ks++) {
            uint32_t ah[MI][4], al[MI][4];
            #pragma unroll
            for (int mi = 0; mi < MI; mi++) {
                const int row = wm * WM + mi * 16 + (lane & 15);
                const int col = ks * 16 + (lane >> 4) * 8;
                const uint32_t ad = sAh + (uint32_t)(row * LS + col) * 2u;
                ldsm4(ah[mi], ad);
                if (NPROD == 2) ldsm4(al[mi], ad + AT);
            }
            uint32_t bh[NI][2];
            #pragma unroll
            for (int ni = 0; ni < NI; ni += 2) {
                const int g = lane >> 3;
                const int row = wn * WN + ni * 8 + ((g >> 1) << 3) + (lane & 7);
                const int col = ks * 16 + ((g & 1) << 3);
                const uint32_t bd = sBh + (uint32_t)(row * LS + col) * 2u;
                ldsm4(&bh[ni][0], bd);
            }
            #pragma unroll
            for (int mi = 0; mi < MI; mi++)
                #pragma unroll
                for (int ni = 0; ni < NI; ni++)
                    mma_f16(acc[mi][ni], ah[mi], bh[ni]);
            if (NPROD == 2) {
                #pragma unroll
                for (int mi = 0; mi < MI; mi++)
                    #pragma unroll
                    for (int ni = 0; ni < NI; ni++)
                        mma_f16(acc[mi][ni], al[mi], bh[ni]);
            }
        }
    }

    #pragma unroll
    for (int mi = 0; mi < MI; mi++) {
        #pragma unroll
        for (int ni = 0; ni < NI; ni++) {
            const int r0 = m0 + wm * WM + mi * 16 + (lane >> 2);
            const int cc = n0 + wn * WN + ni * 8 + ((lane & 3) << 1);
            const float b0 = bias[cc], b1 = bias[cc + 1];
            float v0 = acc[mi][ni][0] + b0;
            float v1 = acc[mi][ni][1] + b1;
            float v2 = acc[mi][ni][2] + b0;
            float v3 = acc[mi][ni][3] + b1;
            if (relu) {
                v0 = fmaxf(v0, 0.0f); v1 = fmaxf(v1, 0.0f);
                v2 = fmaxf(v2, 0.0f); v3 = fmaxf(v3, 0.0f);
            }
            if (C) {
                *(float2*)(C + (size_t)r0 * (size_t)ldc + cc)       = make_float2(v0, v1);
                *(float2*)(C + (size_t)(r0 + 8) * (size_t)ldc + cc) = make_float2(v2, v3);
            }
            if (Ohi) {
                __half h0, l0, h1, l1, h2, l2, h3, l3;
                split_h(v0, h0, l0); split_h(v1, h1, l1);
                split_h(v2, h2, l2); split_h(v3, h3, l3);
                *(uint32_t*)(Ohi + (size_t)r0 * ldo + cc)       = pack_h2(h0, h1);
                *(uint32_t*)(Olo + (size_t)r0 * ldo + cc)       = pack_h2(l0, l1);
                *(uint32_t*)(Ohi + (size_t)(r0 + 8) * ldo + cc) = pack_h2(h2, h3);
                *(uint32_t*)(Olo + (size_t)(r0 + 8) * ldo + cc) = pack_h2(l2, l3);
            }
        }
    }
}

// chain: 64x64, NPROD=2, 4 stages -> 4*(2*5120 + 5120) = 61440 B
#define SMEM_SMALL (4 * (2 * 64 * 40 * 2 + 64 * 40 * 2))
// unembed: 128x256, NPROD=1, 3 stages -> 3*(10240 + 20480) = 92160 B
#define SMEM_UNE   (3 * (128 * 40 * 2 + 256 * 40 * 2))

typedef void (*gemm_t)(const __half*, const __half*, const __half*,
                       const float*, float*, long long,
                       __half*, __half*, int, int, int);

// ---------------------------------------------------------------------------
// Host orchestration
// ---------------------------------------------------------------------------
extern "C" void kernel_launch(void* const* d_in, const int* in_sizes, int n_in,
                              void* d_out, int out_size) {
    const int*   tok     = (const int*)  d_in[0];
    const float* hidden  = (const float*)d_in[1];
    const float* emb     = (const float*)d_in[2];
    const float* rms_w   = (const float*)d_in[3];
    const float* proj_w  = (const float*)d_in[4];
    const float* proj_b  = (const float*)d_in[5];
    const float* sa_wv   = (const float*)d_in[6];
    const float* sa_bv   = (const float*)d_in[7];
    const float* sa_wo   = (const float*)d_in[8];
    const float* sa_bo   = (const float*)d_in[9];
    const float* ca_wv   = (const float*)d_in[10];
    const float* ca_bv   = (const float*)d_in[11];
    const float* ca_wo   = (const float*)d_in[12];
    const float* ca_bo   = (const float*)d_in[13];
    const float* ln1_w   = (const float*)d_in[14];
    const float* ln1_b   = (const float*)d_in[15];
    const float* ln2_w   = (const float*)d_in[16];
    const float* ln2_b   = (const float*)d_in[17];
    const float* ln3_w   = (const float*)d_in[18];
    const float* ln3_b   = (const float*)d_in[19];
    const float* ff_w1   = (const float*)d_in[20];
    const float* ff_b1   = (const float*)d_in[21];
    const float* ff_w2   = (const float*)d_in[22];
    const float* ff_b2   = (const float*)d_in[23];
    const float* unemb_w = (const float*)d_in[24];
    const float* unemb_b = (const float*)d_in[25];
    float* out = (float*)d_out;

    static __half *wh = nullptr;
    static __half *xch = nullptr, *xcl = nullptr;
    static __half *xhB = nullptr, *xlB = nullptr;
    static __half *t1h = nullptr, *t1l = nullptr;
    static float *x = nullptr, *t2 = nullptr;
    static cudaStream_t s2 = nullptr;
    static cudaEvent_t evStart = nullptr, evDone = nullptr, evH[HH] = {};
    if (!wh) {
        cudaGetSymbolAddress((void**)&wh,  g_wh);
        cudaGetSymbolAddress((void**)&xch, g_xc_hi);
        cudaGetSymbolAddress((void**)&xcl, g_xc_lo);
        cudaGetSymbolAddress((void**)&xhB, g_x_hi);
        cudaGetSymbolAddress((void**)&xlB, g_x_lo);
        cudaGetSymbolAddress((void**)&t1h, g_t1_hi);
        cudaGetSymbolAddress((void**)&t1l, g_t1_lo);
        cudaGetSymbolAddress((void**)&x,   g_x);
        cudaGetSymbolAddress((void**)&t2,  g_t2);
        cudaFuncSetAttribute((void*)(gemm_t)gemm_fp16<64, 64, 2, 4, 256, 4, 2>,
                             cudaFuncAttributeMaxDynamicSharedMemorySize, SMEM_SMALL);
        cudaFuncSetAttribute((void*)(gemm_t)gemm_fp16<128, 256, 4, 4, 512, 3, 1>,
                             cudaFuncAttributeMaxDynamicSharedMemorySize, SMEM_UNE);
        cudaStreamCreateWithFlags(&s2, cudaStreamNonBlocking);
        cudaEventCreateWithFlags(&evStart, cudaEventDisableTiming);
        cudaEventCreateWithFlags(&evDone,  cudaEventDisableTiming);
        for (int i = 0; i < HH; i++) cudaEventCreateWithFlags(&evH[i], cudaEventDisableTiming);
    }

    // fork s2 off the capture stream
    cudaEventRecord(evStart, 0);
    cudaStreamWaitEvent(s2, evStart, 0);

    // unembed weight conversion on s2 (only unembed consumes it)
    conv_w<<<2048, 256, 0, s2>>>(unemb_w, wh + OFF_UNE, 32768000 / 4);

    // chain weight conversions on main stream
    conv_w<<<1024, 256>>>(proj_w,  wh + OFF_PROJ, 8388608 / 4);
    conv_w<<<1024, 256>>>(sa_wv,   wh + OFF_SAWV, 4194304 / 4);
    conv_w<<<1024, 256>>>(sa_wo,   wh + OFF_SAWO, 4194304 / 4);
    conv_w<<<1024, 256>>>(ca_wv,   wh + OFF_CAWV, 4194304 / 4);
    conv_w<<<1024, 256>>>(ca_wo,   wh + OFF_CAWO, 4194304 / 4);
    conv_w<<<1024, 256>>>(ff_w1,   wh + OFF_FF1,  8388608 / 4);
    conv_w<<<1024, 256>>>(ff_w2,   wh + OFF_FF2,  8388608 / 4);

    init_h_kernel<<<MM, 256>>>(hidden, x);

    for (int h = 0; h < HH; h++) {
        __half *XH = xhB + (size_t)h * MM * DD;
        __half *XL = xlB + (size_t)h * MM * DD;

        prep_kernel<<<dim3(MM, 2), 256>>>(tok, emb, x, rms_w, xch, xcl, h);

        gemm_fp16<64, 64, 2, 4, 256, 4, 2><<<dim3(MM / 64, DD / 64), 256, SMEM_SMALL>>>(
            xch, xcl, wh + OFF_PROJ + (size_t)h * 2097152,
            proj_b + (size_t)h * DD, x, DD, XH, XL, DD, 2 * DD, 0);

        gemm_fp16<64, 64, 2, 4, 256, 4, 2><<<dim3(MM / 64, DD / 64), 256, SMEM_SMALL>>>(
            XH, XL, wh + OFF_SAWV + (size_t)h * 1048576,
            sa_bv + (size_t)h * DD, nullptr, 0, t1h, t1l, DD, DD, 0);
        gemm_fp16<64, 64, 2, 4, 256, 4, 2><<<dim3(MM / 64, DD / 64), 256, SMEM_SMALL>>>(
            t1h, t1l, wh + OFF_SAWO + (size_t)h * 1048576,
            sa_bo + (size_t)h * DD, t2, DD, nullptr, nullptr, 0, DD, 0);
        resid_ln_kernel<<<MM, 256>>>(x, t2, ln1_w + (size_t)h * DD, ln1_b + (size_t)h * DD, XH, XL);

        gemm_fp16<64, 64, 2, 4, 256, 4, 2><<<dim3(MM / 64, DD / 64), 256, SMEM_SMALL>>>(
            XH, XL, wh + OFF_CAWV + (size_t)h * 1048576,
            ca_bv + (size_t)h * DD, nullptr, 0, t1h, t1l, DD, DD, 0);
        gemm_fp16<64, 64, 2, 4, 256, 4, 2><<<dim3(MM / 64, DD / 64), 256, SMEM_SMALL>>>(
            t1h, t1l, wh + OFF_CAWO + (size_t)h * 1048576,
            ca_bo + (size_t)h * DD, t2, DD, nullptr, nullptr, 0, DD, 0);
        resid_ln_kernel<<<MM, 256>>>(x, t2, ln2_w + (size_t)h * DD, ln2_b + (size_t)h * DD, XH, XL);

        gemm_fp16<64, 64, 2, 4, 256, 4, 2><<<dim3(MM / 64, DFF / 64), 256, SMEM_SMALL>>>(
            XH, XL, wh + OFF_FF1 + (size_t)h * 2097152,
            ff_b1 + (size_t)h * DFF, nullptr, 0, t1h, t1l, DFF, DD, 1);
        gemm_fp16<64, 64, 2, 4, 256, 4, 2><<<dim3(MM / 64, DD / 64), 256, SMEM_SMALL>>>(
            t1h, t1l, wh + OFF_FF2 + (size_t)h * 2097152,
            ff_b2 + (size_t)h * DD, t2, DD, nullptr, nullptr, 0, DFF, 0);
        resid_ln_kernel<<<MM, 256>>>(x, t2, ln3_w + (size_t)h * DD, ln3_b + (size_t)h * DD, XH, XL);

        // hand final activations of head h to stream s2 for the unembed GEMM
        cudaEventRecord(evH[h], 0);
        cudaStreamWaitEvent(s2, evH[h], 0);
        gemm_fp16<128, 256, 4, 4, 512, 3, 1><<<dim3(MM / 128, VV / 256), 512, SMEM_UNE, s2>>>(
            XH, nullptr, wh + OFF_UNE,
            unemb_b, out + (size_t)h * VV, (long long)HH * VV, nullptr, nullptr, 0, DD, 0);
    }

    // join s2 back into the capture stream
    cudaEventRecord(evDone, s2);
    cudaStreamWaitEvent(0, evDone, 0);
}